// round 16
// baseline (speedup 1.0000x reference)
#include <cuda_runtime.h>
#include <math.h>
#include <stdint.h>

#define Bb   8
#define Cc   256
#define Hh   64
#define Ww   64
#define Gg   16
#define Dd   16
#define Pp   3
#define CRr  64
#define NT   49
#define NTP  52        // taps padded: 4 warps * 13
#define TPW  13
#define KKG  784
#define HW   4096
#define EPSf 1e-5f

// ---------------- packed f32x2 helpers ---------------------------------------
typedef unsigned long long ull;
#define FMA2(acc, a, b) asm("fma.rn.f32x2 %0, %1, %2, %0;" : "+l"(acc) : "l"(a), "l"(b))
#define ADD2(acc, a)    asm("add.rn.f32x2 %0, %0, %1;"     : "+l"(acc) : "l"(a))
#define PACK2(d, lo, hi) asm("mov.b64 %0, {%1, %2};" : "=l"(d) : "f"(lo), "f"(hi))
#define PACK2U(d, u)     asm("mov.b64 %0, {%1, %1};" : "=l"(d) : "r"(u))
#define SPLIT2U(lo, hi, s) asm("mov.b64 {%0, %1}, %2;" : "=r"(lo), "=r"(hi) : "l"(s))
#define UNPACK2(lo, hi, s) asm("mov.b64 {%0, %1}, %2;" : "=f"(lo), "=f"(hi) : "l"(s))
#define LDSV2(lo, hi, addr) \
    asm volatile("ld.shared.v2.u64 {%0, %1}, [%2];" : "=l"(lo), "=l"(hi) : "r"(addr))
#define STSV2(addr, lo, hi) \
    asm volatile("st.shared.v2.u64 [%0], {%1, %2};" :: "r"(addr), "l"(lo), "l"(hi))
#define LDS64(dst, addr) \
    asm volatile("ld.shared.b64 %0, [%1];" : "=l"(dst) : "r"(addr))

static __device__ __forceinline__ uint32_t saddr(const void* p) {
    return (uint32_t)__cvta_generic_to_shared(p);
}

// ---------------- device-global scratch --------------------------------------
__device__ float g_wrT[Cc * CRr];                         // reduce weights [k][m]
__device__ float g_br[CRr];
// span weights, plain pairs: [g][warp(4)][k2(32)][slot(13)] x {wk, wk+1}
__device__ __align__(16) float g_ws8[Gg * 4 * 32 * TPW * 2];
__device__ float g_bsp[KKG];
__device__ float g_r[(size_t)Bb * CRr * HW];              // reduce output [b][c][hw]

// ---------------- weight preparation (warp per row) ---------------------------
__global__ __launch_bounds__(256) void prep_weights(
        const float* __restrict__ v_reduce, const float* __restrict__ g_reduce,
        const float* __restrict__ b_reduce, const float* __restrict__ bn_gamma,
        const float* __restrict__ bn_beta,  const float* __restrict__ bn_mean,
        const float* __restrict__ bn_var,   const float* __restrict__ v_span,
        const float* __restrict__ g_span,   const float* __restrict__ b_span) {
    int row  = blockIdx.x * 8 + (threadIdx.x >> 5);
    int lane = threadIdx.x & 31;
    if (row < CRr) {
        float v[8];
        float s = 0.f;
#pragma unroll
        for (int i = 0; i < 8; i++) {
            v[i] = v_reduce[row * Cc + lane + i * 32];
            s += v[i] * v[i];
        }
#pragma unroll
        for (int off = 16; off > 0; off >>= 1)
            s += __shfl_xor_sync(0xffffffffu, s, off);
        float scale = bn_gamma[row] * rsqrtf(bn_var[row] + EPSf);
        float wmul  = g_reduce[row] / sqrtf(s) * scale;
#pragma unroll
        for (int i = 0; i < 8; i++)
            g_wrT[(lane + i * 32) * CRr + row] = v[i] * wmul;
        if (lane == 0)
            g_br[row] = (b_reduce[row] - bn_mean[row]) * scale + bn_beta[row];
    } else if (row < CRr + KKG) {
        int o = row - CRr;            // o = tap*16 + g
        int tap = o >> 4;
        int gq  = o & 15;
        float v0 = v_span[o * CRr + lane];
        float v1 = v_span[o * CRr + 32 + lane];
        float s = v0 * v0 + v1 * v1;
#pragma unroll
        for (int off = 16; off > 0; off >>= 1)
            s += __shfl_xor_sync(0xffffffffu, s, off);
        float wmul = g_span[o] / sqrtf(s);
        float w0 = v0 * wmul, w1 = v1 * wmul;
        int wp = tap / TPW, slot = tap % TPW;
        int c0 = lane, c1 = lane + 32;
        g_ws8[((((gq * 4 + wp) * 32 + (c0 >> 1)) * TPW + slot) << 1) + (c0 & 1)] = w0;
        g_ws8[((((gq * 4 + wp) * 32 + (c1 >> 1)) * TPW + slot) << 1) + (c1 & 1)] = w1;
        if (lane == 0) g_bsp[o] = b_span[o];
    } else if (row < CRr + KKG + Gg * 3) {
        int p = row - (CRr + KKG);    // zero-pad taps 49..51
        int gq = p / 3;
        int tap = NT + p % 3;
        int wp = tap / TPW, slot = tap % TPW;
        int c0 = lane, c1 = lane + 32;
        g_ws8[((((gq * 4 + wp) * 32 + (c0 >> 1)) * TPW + slot) << 1) + (c0 & 1)] = 0.f;
        g_ws8[((((gq * 4 + wp) * 32 + (c1 >> 1)) * TPW + slot) << 1) + (c1 & 1)] = 0.f;
    }
}

// ---------------- reduce GEMM: m=64 x n=128 px, 256 CTAs ----------------------
__global__ __launch_bounds__(256) void reduce_gemm(const float* __restrict__ x) {
    __shared__ float As[16][64];
    __shared__ float Bs[16][128];
    int b  = blockIdx.z;
    int n0 = blockIdx.x * 128;
    int tid = threadIdx.x;
    int ty = tid >> 5;
    int tx = tid & 31;
    const float* xb = x + (size_t)b * Cc * HW;

    ull acc2[4][4];
#pragma unroll
    for (int i = 0; i < 4; i++)
#pragma unroll
        for (int j = 0; j < 4; j++) acc2[i][j] = 0ull;

    for (int k0 = 0; k0 < Cc; k0 += 16) {
        {
            int kr = tid >> 4, m4 = (tid & 15) * 4;
            *(float4*)&As[kr][m4] = *(const float4*)&g_wrT[(k0 + kr) * CRr + m4];
        }
#pragma unroll
        for (int q = 0; q < 2; q++) {
            int f = q * 256 + tid;
            int kr = f >> 5, c4 = (f & 31) * 4;
            *(float4*)&Bs[kr][c4] = *(const float4*)(xb + (size_t)(k0 + kr) * HW + n0 + c4);
        }
        __syncthreads();
#pragma unroll
        for (int k = 0; k < 16; k++) {
            ull a0, a1, a2, a3;
            LDSV2(a0, a1, saddr(&As[k][ty * 8]));
            LDSV2(a2, a3, saddr(&As[k][ty * 8 + 4]));
            float4 bv = *(float4*)&Bs[k][tx * 4];
            float bs[4] = {bv.x, bv.y, bv.z, bv.w};
            ull bd[4];
#pragma unroll
            for (int j = 0; j < 4; j++) PACK2(bd[j], bs[j], bs[j]);
            ull aa[4] = {a0, a1, a2, a3};
#pragma unroll
            for (int i = 0; i < 4; i++)
#pragma unroll
                for (int j = 0; j < 4; j++)
                    FMA2(acc2[i][j], aa[i], bd[j]);
        }
        __syncthreads();
    }

    float bia[8];
#pragma unroll
    for (int i = 0; i < 8; i++) bia[i] = g_br[ty * 8 + i];
    float* rb = g_r + (size_t)b * CRr * HW;
#pragma unroll
    for (int i = 0; i < 4; i++) {
        float f[2][4];
#pragma unroll
        for (int j = 0; j < 4; j++) {
            float lo, hi;
            UNPACK2(lo, hi, acc2[i][j]);
            f[0][j] = fmaxf(lo + bia[2 * i], 0.f);
            f[1][j] = fmaxf(hi + bia[2 * i + 1], 0.f);
        }
#pragma unroll
        for (int h = 0; h < 2; h++) {
            int m = ty * 8 + 2 * i + h;
            *(float4*)(rb + (size_t)m * HW + n0 + tx * 4) =
                make_float4(f[h][0], f[h][1], f[h][2], f[h][3]);
        }
    }
}

// ---------------- fused span + involution (70.9KB, 3 CTAs/SM) -----------------
#define TSX  16
#define TSY  8
#define NPX  128
#define XDX  22
#define XDY  14
#define XSTR 20
#define KST  132
#define WSB  (32 * TPW * 8)             // 3328 B per warp
#define OFF_RS   0                      // 64k x 128px fp32   = 32768 B
#define OFF_KER  0                      // overlays rs (25872 <= 32768)
#define OFF_WS   32768                  // 4 x 3328           = 13312 B
#define OFF_XS   46080                  // 308 x 20 x 4       = 24640 B
#define OFF_BS   70720                  // 52 x 4
#define SMEM_REQ 70928

extern __shared__ char smraw[];

__global__ __launch_bounds__(256, 3) void fused_kernel(
        const float* __restrict__ x, float* __restrict__ out) {
    int tid  = threadIdx.x;
    int wid  = tid >> 5;
    int lane = tid & 31;
    int bz = blockIdx.z;
    int b = bz >> 4, g = bz & 15;
    int h0 = blockIdx.y * TSY, w0 = blockIdx.x * TSX;
    uint32_t sb = saddr(smraw);

    // ---- cooperative loads: rs + ws + bias --------------------------------------
    {
        const float* rb = g_r + (size_t)b * CRr * HW;
        float* rs = (float*)(smraw + OFF_RS);
#pragma unroll
        for (int it = 0; it < 8; it++) {
            int i = tid + it * 256;          // 2048 float4
            int c = i >> 5, rem = i & 31;
            int y = rem >> 2, x4 = (rem & 3) << 2;
            float4 v = *(const float4*)(rb + (size_t)c * HW + (h0 + y) * Ww + w0 + x4);
            *(float4*)(rs + c * NPX + y * 16 + x4) = v;
        }
    }
    {
        const uint4* src = (const uint4*)g_ws8 + (size_t)g * 832;
        uint4* dst = (uint4*)(smraw + OFF_WS);
#pragma unroll
        for (int it = 0; it < 4; it++) {
            int i = tid + it * 256;
            if (i < 832) dst[i] = src[i];
        }
    }
    if (tid < NTP)
        ((float*)(smraw + OFF_BS))[tid] = (tid < NT) ? g_bsp[tid * Gg + g] : 0.f;
    __syncthreads();

    // ---- phase 1 compute (warps 0-3, rs double-buffered) | halo (warps 4-7) -----
    ull acc2[TPW][2];
    if (wid < 4) {
#pragma unroll
        for (int i = 0; i < TPW; i++) { acc2[i][0] = 0ull; acc2[i][1] = 0ull; }

        uint32_t rs_a = sb + OFF_RS + lane * 16;
        uint32_t ws_a = sb + OFF_WS + wid * WSB;
        ull b0, b1, c0, c1;
        LDSV2(b0, b1, rs_a);
        LDSV2(c0, c1, rs_a + 512);
#pragma unroll 2
        for (int k2 = 0; k2 < 32; k2++) {
            // prefetch next k2's rs (k2=31 overreads into ws region: harmless)
            ull nb0, nb1, nc0, nc1;
            uint32_t rn = rs_a + (k2 + 1) * 1024;
            LDSV2(nb0, nb1, rn);
            LDSV2(nc0, nc1, rn + 512);
            uint32_t wa = ws_a + k2 * (TPW * 8);
#pragma unroll
            for (int i = 0; i < TPW; i++) {
                ull wv;
                LDS64(wv, wa + i * 8);    // broadcast: {wk, wk+1}
                uint32_t wl, wh;
                SPLIT2U(wl, wh, wv);
                ull a0, a1;
                PACK2U(a0, wl);
                PACK2U(a1, wh);
                FMA2(acc2[i][0], a0, b0);
                FMA2(acc2[i][1], a0, b1);
                FMA2(acc2[i][0], a1, c0);
                FMA2(acc2[i][1], a1, c1);
            }
            b0 = nb0; b1 = nb1; c0 = nc0; c1 = nc1;
        }
    } else {
        float* xs = (float*)(smraw + OFF_XS);
        const float* xbg = x + (size_t)(b * Cc + g * Dd) * HW;
        int lt = tid - 128;               // 0..127
        for (int idx = lt; idx < Dd * XDY * XDX; idx += 128) {
            int d  = idx / (XDY * XDX);
            int rr = idx - d * (XDY * XDX);
            int yy = rr / XDX;
            int xx = rr - yy * XDX;
            int gy = h0 + yy - Pp;
            int gx = w0 + xx - Pp;
            float v = 0.f;
            if (gy >= 0 && gy < Hh && gx >= 0 && gx < Ww)
                v = xbg[(size_t)d * HW + gy * Ww + gx];
            xs[(yy * XDX + xx) * XSTR + d] = v;
        }
    }
    // all rs reads complete past this barrier -> safe to overlay ker on rs
    __syncthreads();

    // ---- phase 1 epilogue: bias + ker store (into overlaid region) ---------------
    if (wid < 4) {
        float* bs = (float*)(smraw + OFF_BS);
#pragma unroll
        for (int i = 0; i < TPW; i++) {
            int tap = wid * TPW + i;
            if (tap < NT) {
                ull bp;
                float bv = bs[tap];
                PACK2(bp, bv, bv);
                ADD2(acc2[i][0], bp);
                ADD2(acc2[i][1], bp);
                STSV2(sb + OFF_KER + tap * (KST * 4) + lane * 16,
                      acc2[i][0], acc2[i][1]);
            }
        }
    }
    __syncthreads();

    // ---- phase 2: involution (warps 0-3: 4px x 4d sliding window) --------------
    if (wid < 4) {
        float* kerp = (float*)(smraw + OFF_KER);
        int pg = tid >> 2;          // 32 pixel groups of 4
        int dq = tid & 3;
        int p0 = pg * 4;
        int y  = p0 >> 4;           // 0..7
        int x0 = p0 & 15;           // 0,4,8,12
        int d0 = dq * 4;

        ull accb[2][4];             // [d-pair][px]
#pragma unroll
        for (int dp = 0; dp < 2; dp++)
#pragma unroll
            for (int px = 0; px < 4; px++) accb[dp][px] = 0ull;

        uint32_t xs_a = sb + OFF_XS;
#pragma unroll
        for (int ki = 0; ki < 7; ki++) {
            uint32_t xrow = xs_a + (((y + ki) * XDX + x0) * XSTR + d0) * 4;
            ull cur[4][2];
#pragma unroll
            for (int p = 0; p < 3; p++)
                LDSV2(cur[p][0], cur[p][1], xrow + p * (XSTR * 4));
#pragma unroll
            for (int kj = 0; kj < 7; kj++) {
                {
                    int s = (kj + 3) & 3;
                    LDSV2(cur[s][0], cur[s][1], xrow + (kj + 3) * (XSTR * 4));
                }
                float4 kv = *(float4*)(kerp + (ki * 7 + kj) * KST + p0);
                float kvv[4] = {kv.x, kv.y, kv.z, kv.w};
                ull kd[4];
#pragma unroll
                for (int px = 0; px < 4; px++) PACK2(kd[px], kvv[px], kvv[px]);
#pragma unroll
                for (int px = 0; px < 4; px++) {
                    int s = (kj + px) & 3;
                    FMA2(accb[0][px], cur[s][0], kd[px]);
                    FMA2(accb[1][px], cur[s][1], kd[px]);
                }
            }
        }

        float* ob = out + (size_t)(b * Cc + g * Dd + d0) * HW + (h0 + y) * Ww + w0 + x0;
#pragma unroll
        for (int dp = 0; dp < 2; dp++) {
            float lo[4], hi[4];
#pragma unroll
            for (int px = 0; px < 4; px++) UNPACK2(lo[px], hi[px], accb[dp][px]);
            *(float4*)(ob + (size_t)(2 * dp) * HW)     = make_float4(lo[0], lo[1], lo[2], lo[3]);
            *(float4*)(ob + (size_t)(2 * dp + 1) * HW) = make_float4(hi[0], hi[1], hi[2], hi[3]);
        }
    }
}

// ---------------- launcher -----------------------------------------------------
extern "C" void kernel_launch(void* const* d_in, const int* in_sizes, int n_in,
                              void* d_out, int out_size) {
    const float* x        = (const float*)d_in[0];
    const float* v_reduce = (const float*)d_in[1];
    const float* g_reduce = (const float*)d_in[2];
    const float* b_reduce = (const float*)d_in[3];
    const float* bn_gamma = (const float*)d_in[4];
    const float* bn_beta  = (const float*)d_in[5];
    const float* bn_mean  = (const float*)d_in[6];
    const float* bn_var   = (const float*)d_in[7];
    const float* v_span   = (const float*)d_in[8];
    const float* g_span   = (const float*)d_in[9];
    const float* b_span   = (const float*)d_in[10];
    float* out = (float*)d_out;

    static bool attr_set = false;
    if (!attr_set) {
        cudaFuncSetAttribute(fused_kernel,
                             cudaFuncAttributeMaxDynamicSharedMemorySize, SMEM_REQ);
        attr_set = true;
    }

    prep_weights<<<112, 256>>>(v_reduce, g_reduce, b_reduce,
                               bn_gamma, bn_beta, bn_mean, bn_var,
                               v_span, g_span, b_span);

    reduce_gemm<<<dim3(HW / 128, 1, Bb), 256>>>(x);

    fused_kernel<<<dim3(Ww / TSX, Hh / TSY, Bb * Gg), 256, SMEM_REQ>>>(x, out);
}

// round 17
// speedup vs baseline: 1.1814x; 1.1814x over previous
#include <cuda_runtime.h>
#include <math.h>
#include <stdint.h>

#define Bb   8
#define Cc   256
#define Hh   64
#define Ww   64
#define Gg   16
#define Dd   16
#define Pp   3
#define CRr  64
#define NT   49
#define NTP  52        // taps padded: 4 warps * 13
#define TPW  13
#define KKG  784
#define HW   4096
#define EPSf 1e-5f

// ---------------- packed f32x2 helpers ---------------------------------------
typedef unsigned long long ull;
#define FMA2(acc, a, b) asm("fma.rn.f32x2 %0, %1, %2, %0;" : "+l"(acc) : "l"(a), "l"(b))
#define ADD2(acc, a)    asm("add.rn.f32x2 %0, %0, %1;"     : "+l"(acc) : "l"(a))
#define PACK2(d, lo, hi) asm("mov.b64 %0, {%1, %2};" : "=l"(d) : "f"(lo), "f"(hi))
#define PACK2U(d, u)     asm("mov.b64 %0, {%1, %1};" : "=l"(d) : "r"(u))
#define SPLIT2U(lo, hi, s) asm("mov.b64 {%0, %1}, %2;" : "=r"(lo), "=r"(hi) : "l"(s))
#define UNPACK2(lo, hi, s) asm("mov.b64 {%0, %1}, %2;" : "=f"(lo), "=f"(hi) : "l"(s))
#define LDSV2(lo, hi, addr) \
    asm volatile("ld.shared.v2.u64 {%0, %1}, [%2];" : "=l"(lo), "=l"(hi) : "r"(addr))
#define STSV2(addr, lo, hi) \
    asm volatile("st.shared.v2.u64 [%0], {%1, %2};" :: "r"(addr), "l"(lo), "l"(hi))
#define LDS64(dst, addr) \
    asm volatile("ld.shared.b64 %0, [%1];" : "=l"(dst) : "r"(addr))

static __device__ __forceinline__ uint32_t saddr(const void* p) {
    return (uint32_t)__cvta_generic_to_shared(p);
}

// ---------------- device-global scratch --------------------------------------
__device__ float g_wrT[Cc * CRr];                         // reduce weights [k][m]
__device__ float g_br[CRr];
// span weights, plain pairs: [g][warp(4)][k2(32)][slot(13)] x {wk, wk+1}
__device__ __align__(16) float g_ws8[Gg * 4 * 32 * TPW * 2];
__device__ float g_bsp[KKG];
__device__ float g_r[(size_t)Bb * CRr * HW];              // reduce output [b][c][hw]

// ---------------- weight preparation (warp per row) ---------------------------
__global__ __launch_bounds__(256) void prep_weights(
        const float* __restrict__ v_reduce, const float* __restrict__ g_reduce,
        const float* __restrict__ b_reduce, const float* __restrict__ bn_gamma,
        const float* __restrict__ bn_beta,  const float* __restrict__ bn_mean,
        const float* __restrict__ bn_var,   const float* __restrict__ v_span,
        const float* __restrict__ g_span,   const float* __restrict__ b_span) {
    int row  = blockIdx.x * 8 + (threadIdx.x >> 5);
    int lane = threadIdx.x & 31;
    if (row < CRr) {
        float v[8];
        float s = 0.f;
#pragma unroll
        for (int i = 0; i < 8; i++) {
            v[i] = v_reduce[row * Cc + lane + i * 32];
            s += v[i] * v[i];
        }
#pragma unroll
        for (int off = 16; off > 0; off >>= 1)
            s += __shfl_xor_sync(0xffffffffu, s, off);
        float scale = bn_gamma[row] * rsqrtf(bn_var[row] + EPSf);
        float wmul  = g_reduce[row] / sqrtf(s) * scale;
#pragma unroll
        for (int i = 0; i < 8; i++)
            g_wrT[(lane + i * 32) * CRr + row] = v[i] * wmul;
        if (lane == 0)
            g_br[row] = (b_reduce[row] - bn_mean[row]) * scale + bn_beta[row];
    } else if (row < CRr + KKG) {
        int o = row - CRr;            // o = tap*16 + g
        int tap = o >> 4;
        int gq  = o & 15;
        float v0 = v_span[o * CRr + lane];
        float v1 = v_span[o * CRr + 32 + lane];
        float s = v0 * v0 + v1 * v1;
#pragma unroll
        for (int off = 16; off > 0; off >>= 1)
            s += __shfl_xor_sync(0xffffffffu, s, off);
        float wmul = g_span[o] / sqrtf(s);
        float w0 = v0 * wmul, w1 = v1 * wmul;
        int wp = tap / TPW, slot = tap % TPW;
        int c0 = lane, c1 = lane + 32;
        g_ws8[((((gq * 4 + wp) * 32 + (c0 >> 1)) * TPW + slot) << 1) + (c0 & 1)] = w0;
        g_ws8[((((gq * 4 + wp) * 32 + (c1 >> 1)) * TPW + slot) << 1) + (c1 & 1)] = w1;
        if (lane == 0) g_bsp[o] = b_span[o];
    } else if (row < CRr + KKG + Gg * 3) {
        int p = row - (CRr + KKG);    // zero-pad taps 49..51
        int gq = p / 3;
        int tap = NT + p % 3;
        int wp = tap / TPW, slot = tap % TPW;
        int c0 = lane, c1 = lane + 32;
        g_ws8[((((gq * 4 + wp) * 32 + (c0 >> 1)) * TPW + slot) << 1) + (c0 & 1)] = 0.f;
        g_ws8[((((gq * 4 + wp) * 32 + (c1 >> 1)) * TPW + slot) << 1) + (c1 & 1)] = 0.f;
    }
}

// ---------------- reduce GEMM: m=64 x n=128 px, 256 CTAs ----------------------
__global__ __launch_bounds__(256) void reduce_gemm(const float* __restrict__ x) {
    __shared__ float As[16][64];
    __shared__ float Bs[16][128];
    int b  = blockIdx.z;
    int n0 = blockIdx.x * 128;
    int tid = threadIdx.x;
    int ty = tid >> 5;
    int tx = tid & 31;
    const float* xb = x + (size_t)b * Cc * HW;

    ull acc2[4][4];
#pragma unroll
    for (int i = 0; i < 4; i++)
#pragma unroll
        for (int j = 0; j < 4; j++) acc2[i][j] = 0ull;

    for (int k0 = 0; k0 < Cc; k0 += 16) {
        {
            int kr = tid >> 4, m4 = (tid & 15) * 4;
            *(float4*)&As[kr][m4] = *(const float4*)&g_wrT[(k0 + kr) * CRr + m4];
        }
#pragma unroll
        for (int q = 0; q < 2; q++) {
            int f = q * 256 + tid;
            int kr = f >> 5, c4 = (f & 31) * 4;
            *(float4*)&Bs[kr][c4] = *(const float4*)(xb + (size_t)(k0 + kr) * HW + n0 + c4);
        }
        __syncthreads();
#pragma unroll
        for (int k = 0; k < 16; k++) {
            ull a0, a1, a2, a3;
            LDSV2(a0, a1, saddr(&As[k][ty * 8]));
            LDSV2(a2, a3, saddr(&As[k][ty * 8 + 4]));
            float4 bv = *(float4*)&Bs[k][tx * 4];
            float bs[4] = {bv.x, bv.y, bv.z, bv.w};
            ull bd[4];
#pragma unroll
            for (int j = 0; j < 4; j++) PACK2(bd[j], bs[j], bs[j]);
            ull aa[4] = {a0, a1, a2, a3};
#pragma unroll
            for (int i = 0; i < 4; i++)
#pragma unroll
                for (int j = 0; j < 4; j++)
                    FMA2(acc2[i][j], aa[i], bd[j]);
        }
        __syncthreads();
    }

    float bia[8];
#pragma unroll
    for (int i = 0; i < 8; i++) bia[i] = g_br[ty * 8 + i];
    float* rb = g_r + (size_t)b * CRr * HW;
#pragma unroll
    for (int i = 0; i < 4; i++) {
        float f[2][4];
#pragma unroll
        for (int j = 0; j < 4; j++) {
            float lo, hi;
            UNPACK2(lo, hi, acc2[i][j]);
            f[0][j] = fmaxf(lo + bia[2 * i], 0.f);
            f[1][j] = fmaxf(hi + bia[2 * i + 1], 0.f);
        }
#pragma unroll
        for (int h = 0; h < 2; h++) {
            int m = ty * 8 + 2 * i + h;
            *(float4*)(rb + (size_t)m * HW + n0 + tx * 4) =
                make_float4(f[h][0], f[h][1], f[h][2], f[h][3]);
        }
    }
}

// ---------------- fused span + involution (70.9KB, 3 CTAs/SM) -----------------
#define TSX  16
#define TSY  8
#define NPX  128
#define XDX  22
#define XDY  14
#define XSTR 20
#define KST  132
#define WSB  (32 * TPW * 8)             // 3328 B per warp
#define OFF_RS   0                      // 64k x 128px fp32   = 32768 B
#define OFF_KER  0                      // overlays rs (25872 <= 32768)
#define OFF_WS   32768                  // 4 x 3328           = 13312 B
#define OFF_XS   46080                  // 308 x 20 x 4       = 24640 B
#define OFF_BS   70720                  // 52 x 4
#define SMEM_REQ 70928

extern __shared__ char smraw[];

__global__ __launch_bounds__(256, 3) void fused_kernel(
        const float* __restrict__ x, float* __restrict__ out) {
    int tid  = threadIdx.x;
    int wid  = tid >> 5;
    int lane = tid & 31;
    int bz = blockIdx.z;
    int b = bz >> 4, g = bz & 15;
    int h0 = blockIdx.y * TSY, w0 = blockIdx.x * TSX;
    uint32_t sb = saddr(smraw);

    // ---- cooperative loads: rs + ws + bias --------------------------------------
    {
        const float* rb = g_r + (size_t)b * CRr * HW;
        float* rs = (float*)(smraw + OFF_RS);
#pragma unroll
        for (int it = 0; it < 8; it++) {
            int i = tid + it * 256;          // 2048 float4
            int c = i >> 5, rem = i & 31;
            int y = rem >> 2, x4 = (rem & 3) << 2;
            float4 v = *(const float4*)(rb + (size_t)c * HW + (h0 + y) * Ww + w0 + x4);
            *(float4*)(rs + c * NPX + y * 16 + x4) = v;
        }
    }
    {
        const uint4* src = (const uint4*)g_ws8 + (size_t)g * 832;
        uint4* dst = (uint4*)(smraw + OFF_WS);
#pragma unroll
        for (int it = 0; it < 4; it++) {
            int i = tid + it * 256;
            if (i < 832) dst[i] = src[i];
        }
    }
    if (tid < NTP)
        ((float*)(smraw + OFF_BS))[tid] = (tid < NT) ? g_bsp[tid * Gg + g] : 0.f;
    __syncthreads();

    // ---- phase 1 compute (warps 0-3) | x halo load (warps 4-7) ------------------
    ull acc2[TPW][2];
    if (wid < 4) {
#pragma unroll
        for (int i = 0; i < TPW; i++) { acc2[i][0] = 0ull; acc2[i][1] = 0ull; }

        uint32_t rs_a = sb + OFF_RS + lane * 16;
        uint32_t ws_a = sb + OFF_WS + wid * WSB;
#pragma unroll 2
        for (int k2 = 0; k2 < 32; k2++) {
            ull b0, b1, c0, c1;
            uint32_t ra = rs_a + k2 * 1024;
            LDSV2(b0, b1, ra);            // k even : px {0,1},{2,3}
            LDSV2(c0, c1, ra + 512);      // k odd
            uint32_t wa = ws_a + k2 * (TPW * 8);
#pragma unroll
            for (int i = 0; i < TPW; i++) {
                ull wv;
                LDS64(wv, wa + i * 8);    // broadcast: {wk, wk+1}
                uint32_t wl, wh;
                SPLIT2U(wl, wh, wv);
                ull a0, a1;
                PACK2U(a0, wl);
                PACK2U(a1, wh);
                FMA2(acc2[i][0], a0, b0);
                FMA2(acc2[i][1], a0, b1);
                FMA2(acc2[i][0], a1, c0);
                FMA2(acc2[i][1], a1, c1);
            }
        }
    } else {
        float* xs = (float*)(smraw + OFF_XS);
        const float* xbg = x + (size_t)(b * Cc + g * Dd) * HW;
        int lt = tid - 128;               // 0..127
        for (int idx = lt; idx < Dd * XDY * XDX; idx += 128) {
            int d  = idx / (XDY * XDX);
            int rr = idx - d * (XDY * XDX);
            int yy = rr / XDX;
            int xx = rr - yy * XDX;
            int gy = h0 + yy - Pp;
            int gx = w0 + xx - Pp;
            float v = 0.f;
            if (gy >= 0 && gy < Hh && gx >= 0 && gx < Ww)
                v = xbg[(size_t)d * HW + gy * Ww + gx];
            xs[(yy * XDX + xx) * XSTR + d] = v;
        }
    }
    // all rs reads complete past this barrier -> safe to overlay ker on rs
    __syncthreads();

    // ---- phase 1 epilogue: bias + ker store (into overlaid region) ---------------
    if (wid < 4) {
        float* bs = (float*)(smraw + OFF_BS);
#pragma unroll
        for (int i = 0; i < TPW; i++) {
            int tap = wid * TPW + i;
            if (tap < NT) {
                ull bp;
                float bv = bs[tap];
                PACK2(bp, bv, bv);
                ADD2(acc2[i][0], bp);
                ADD2(acc2[i][1], bp);
                STSV2(sb + OFF_KER + tap * (KST * 4) + lane * 16,
                      acc2[i][0], acc2[i][1]);
            }
        }
    }
    __syncthreads();

    // ---- phase 2: involution (warps 0-3: 4px x 4d sliding window) --------------
    if (wid < 4) {
        float* kerp = (float*)(smraw + OFF_KER);
        int pg = tid >> 2;          // 32 pixel groups of 4
        int dq = tid & 3;
        int p0 = pg * 4;
        int y  = p0 >> 4;           // 0..7
        int x0 = p0 & 15;           // 0,4,8,12
        int d0 = dq * 4;

        ull accb[2][4];             // [d-pair][px]
#pragma unroll
        for (int dp = 0; dp < 2; dp++)
#pragma unroll
            for (int px = 0; px < 4; px++) accb[dp][px] = 0ull;

        uint32_t xs_a = sb + OFF_XS;
#pragma unroll
        for (int ki = 0; ki < 7; ki++) {
            uint32_t xrow = xs_a + (((y + ki) * XDX + x0) * XSTR + d0) * 4;
            ull cur[4][2];
#pragma unroll
            for (int p = 0; p < 3; p++)
                LDSV2(cur[p][0], cur[p][1], xrow + p * (XSTR * 4));
#pragma unroll
            for (int kj = 0; kj < 7; kj++) {
                {
                    int s = (kj + 3) & 3;
                    LDSV2(cur[s][0], cur[s][1], xrow + (kj + 3) * (XSTR * 4));
                }
                float4 kv = *(float4*)(kerp + (ki * 7 + kj) * KST + p0);
                float kvv[4] = {kv.x, kv.y, kv.z, kv.w};
                ull kd[4];
#pragma unroll
                for (int px = 0; px < 4; px++) PACK2(kd[px], kvv[px], kvv[px]);
#pragma unroll
                for (int px = 0; px < 4; px++) {
                    int s = (kj + px) & 3;
                    FMA2(accb[0][px], cur[s][0], kd[px]);
                    FMA2(accb[1][px], cur[s][1], kd[px]);
                }
            }
        }

        float* ob = out + (size_t)(b * Cc + g * Dd + d0) * HW + (h0 + y) * Ww + w0 + x0;
#pragma unroll
        for (int dp = 0; dp < 2; dp++) {
            float lo[4], hi[4];
#pragma unroll
            for (int px = 0; px < 4; px++) UNPACK2(lo[px], hi[px], accb[dp][px]);
            *(float4*)(ob + (size_t)(2 * dp) * HW)     = make_float4(lo[0], lo[1], lo[2], lo[3]);
            *(float4*)(ob + (size_t)(2 * dp + 1) * HW) = make_float4(hi[0], hi[1], hi[2], hi[3]);
        }
    }
}

// ---------------- launcher -----------------------------------------------------
extern "C" void kernel_launch(void* const* d_in, const int* in_sizes, int n_in,
                              void* d_out, int out_size) {
    const float* x        = (const float*)d_in[0];
    const float* v_reduce = (const float*)d_in[1];
    const float* g_reduce = (const float*)d_in[2];
    const float* b_reduce = (const float*)d_in[3];
    const float* bn_gamma = (const float*)d_in[4];
    const float* bn_beta  = (const float*)d_in[5];
    const float* bn_mean  = (const float*)d_in[6];
    const float* bn_var   = (const float*)d_in[7];
    const float* v_span   = (const float*)d_in[8];
    const float* g_span   = (const float*)d_in[9];
    const float* b_span   = (const float*)d_in[10];
    float* out = (float*)d_out;

    static bool attr_set = false;
    if (!attr_set) {
        cudaFuncSetAttribute(fused_kernel,
                             cudaFuncAttributeMaxDynamicSharedMemorySize, SMEM_REQ);
        attr_set = true;
    }

    prep_weights<<<112, 256>>>(v_reduce, g_reduce, b_reduce,
                               bn_gamma, bn_beta, bn_mean, bn_var,
                               v_span, g_span, b_span);

    reduce_gemm<<<dim3(HW / 128, 1, Bb), 256>>>(x);

    fused_kernel<<<dim3(Ww / TSX, Hh / TSY, Bb * Gg), 256, SMEM_REQ>>>(x, out);
}